// round 2
// baseline (speedup 1.0000x reference)
#include <cuda_runtime.h>

#define NB        131072      // 32768 centers * 4 species
#define MAXE      1048576
#define NCENT_OUT 512         // 16 sh * 32 (species*nmax) floats per center

namespace {

constexpr float PI_F   = 3.14159265358979323846f;
constexpr float NORM_F = 0.17677669529663687f;   // 1/sqrt(32)

__device__ int    g_cnt[NB];
__device__ int    g_off[NB];
__device__ int    g_cur[NB];
__device__ float4 g_edges[MAXE];

// ---------------------------------------------------------------- phase 1
__global__ void k_zero() {
    int i = blockIdx.x * blockDim.x + threadIdx.x;
    if (i < NB) g_cnt[i] = 0;
}

// ---------------------------------------------------------------- phase 2
__global__ void k_hist(const int* __restrict__ cidx,
                       const int* __restrict__ sidx, int n) {
    int e = blockIdx.x * blockDim.x + threadIdx.x;
    if (e < n) atomicAdd(&g_cnt[cidx[e] * 4 + sidx[e]], 1);
}

// ---------------------------------------------------------------- phase 3
// one CTA, 1024 threads, each owns 128 consecutive buckets
__global__ void k_scan() {
    __shared__ int sm[1024];
    int tid  = threadIdx.x;
    int base = tid * 128;
    int sum = 0;
    #pragma unroll 4
    for (int i = 0; i < 128; i++) sum += g_cnt[base + i];
    sm[tid] = sum;
    __syncthreads();
    int mine = sum;
    #pragma unroll
    for (int off = 1; off < 1024; off <<= 1) {
        int v = (tid >= off) ? sm[tid - off] : 0;
        __syncthreads();
        sm[tid] += v;
        __syncthreads();
    }
    int run = sm[tid] - mine;   // exclusive prefix
    for (int i = 0; i < 128; i++) {
        int c = g_cnt[base + i];
        g_off[base + i] = run;
        g_cur[base + i] = run;
        run += c;
    }
}

// ---------------------------------------------------------------- phase 4
__global__ void k_scatter(const float* __restrict__ vec,
                          const int* __restrict__ cidx,
                          const int* __restrict__ sidx, int n) {
    int e = blockIdx.x * blockDim.x + threadIdx.x;
    if (e >= n) return;
    int b = cidx[e] * 4 + sidx[e];
    int p = atomicAdd(&g_cur[b], 1);
    g_edges[p] = make_float4(vec[3 * e], vec[3 * e + 1], vec[3 * e + 2], 0.f);
}

// ---------------------------------------------------------------- phase 5
// epilogue contraction: out_row[k][n] = sum_b M[k][b] * W[l][b][n]
template<int L, int K0, int NK>
__device__ __forceinline__ void epilogue(const float (&M)[8][12],
                                         const float* __restrict__ sW,
                                         float* __restrict__ outp,
                                         int kglob) {
    float4 o0[NK], o1[NK];
    #pragma unroll
    for (int j = 0; j < NK; j++) {
        o0[j] = make_float4(0.f, 0.f, 0.f, 0.f);
        o1[j] = make_float4(0.f, 0.f, 0.f, 0.f);
    }
    #pragma unroll
    for (int b = 0; b < 12; b++) {
        float4 w0 = *reinterpret_cast<const float4*>(&sW[L * 96 + b * 8]);
        float4 w1 = *reinterpret_cast<const float4*>(&sW[L * 96 + b * 8 + 4]);
        #pragma unroll
        for (int j = 0; j < NK; j++) {
            float m = M[K0 + j][b];
            o0[j].x = fmaf(m, w0.x, o0[j].x);
            o0[j].y = fmaf(m, w0.y, o0[j].y);
            o0[j].z = fmaf(m, w0.z, o0[j].z);
            o0[j].w = fmaf(m, w0.w, o0[j].w);
            o1[j].x = fmaf(m, w1.x, o1[j].x);
            o1[j].y = fmaf(m, w1.y, o1[j].y);
            o1[j].z = fmaf(m, w1.z, o1[j].z);
            o1[j].w = fmaf(m, w1.w, o1[j].w);
        }
    }
    #pragma unroll
    for (int j = 0; j < NK; j++) {
        *reinterpret_cast<float4*>(&outp[(kglob + j) * 32])     = o0[j];
        *reinterpret_cast<float4*>(&outp[(kglob + j) * 32 + 4]) = o1[j];
    }
}

__global__ __launch_bounds__(128)
void k_accum(const float* __restrict__ W, float* __restrict__ out) {
    __shared__ float sW[384];
    for (int i = threadIdx.x; i < 384; i += 128) sW[i] = W[i];
    __syncthreads();

    int gtid = blockIdx.x * 128 + threadIdx.x;
    int warp = gtid >> 5;
    int lane = gtid & 31;
    int h      = warp & 1;               // half: k0..7 or k8..15 (warp-uniform)
    int bucket = (warp >> 1) * 32 + lane;
    if (bucket >= NB) return;

    int start = g_off[bucket];
    int cnt   = g_cnt[bucket];
    int c     = bucket >> 2;
    int sp    = bucket & 3;
    float* outp = out + c * NCENT_OUT + sp * 8;

    float M[8][12];
    #pragma unroll
    for (int k = 0; k < 8; k++)
        #pragma unroll
        for (int b = 0; b < 12; b++) M[k][b] = 0.f;

    float4 v = (cnt > 0) ? g_edges[start] : make_float4(0.f, 0.f, 0.f, 0.f);

    for (int i = 0; i < cnt; i++) {
        float4 vn = (i + 1 < cnt) ? g_edges[start + i + 1] : v;  // prefetch

        float vx = v.x, vy = v.y, vz = v.z;
        float r2   = fmaf(vx, vx, fmaf(vy, vy, vz * vz)) + 1e-12f;
        float rinv = rsqrtf(r2);
        float r    = r2 * rinv;
        float x = vx * rinv, y = vy * rinv, z = vz * rinv;

        // phi[b] = sin(pi/5 * r * (b+1)) / r * NORM  via Chebyshev recurrence
        float a = (PI_F / 5.0f) * r;
        float s0, c0;
        __sincosf(a, &s0, &c0);
        float t     = NORM_F * rinv;
        float two_c = 2.0f * c0;
        float phi[12];
        {
            float sm1 = 0.f, sc = s0;
            phi[0] = sc * t;
            #pragma unroll
            for (int n = 1; n < 12; n++) {
                float s1 = fmaf(two_c, sc, -sm1);
                sm1 = sc; sc = s1;
                phi[n] = sc * t;
            }
        }

        float x2 = x * x, y2 = y * y, z2 = z * z;
        float sh[8];
        if (h == 0) {
            sh[0] = 0.28209479177387814f;
            sh[1] = 0.4886025119029199f * y;
            sh[2] = 0.4886025119029199f * z;
            sh[3] = 0.4886025119029199f * x;
            sh[4] = 1.0925484305920792f * x * y;
            sh[5] = 1.0925484305920792f * y * z;
            sh[6] = 0.31539156525252005f * fmaf(3.0f, z2, -1.0f);
            sh[7] = 1.0925484305920792f * x * z;
        } else {
            sh[0] = 0.5462742152960396f * (x2 - y2);                 // k8  (l=2)
            sh[1] = 0.5900435899266435f * y * fmaf(3.0f, x2, -y2);   // k9
            sh[2] = 2.890611442640554f  * x * y * z;                 // k10
            sh[3] = 0.4570457994644658f * y * fmaf(5.0f, z2, -1.0f); // k11
            sh[4] = 0.3731763325901154f * z * fmaf(5.0f, z2, -3.0f); // k12
            sh[5] = 0.4570457994644658f * x * fmaf(5.0f, z2, -1.0f); // k13
            sh[6] = 1.445305721320277f  * z * (x2 - y2);             // k14
            sh[7] = 0.5900435899266435f * x * (x2 - y2);             // k15
        }

        #pragma unroll
        for (int k = 0; k < 8; k++)
            #pragma unroll
            for (int b = 0; b < 12; b++)
                M[k][b] = fmaf(sh[k], phi[b], M[k][b]);

        v = vn;
    }

    if (h == 0) {
        epilogue<0, 0, 1>(M, sW, outp, 0);   // k0        l=0
        epilogue<1, 1, 3>(M, sW, outp, 1);   // k1..k3    l=1
        epilogue<2, 4, 4>(M, sW, outp, 4);   // k4..k7    l=2
    } else {
        epilogue<2, 0, 1>(M, sW, outp, 8);   // k8        l=2
        epilogue<3, 1, 7>(M, sW, outp, 9);   // k9..k15   l=3
    }
}

} // namespace

extern "C" void kernel_launch(void* const* d_in, const int* in_sizes, int n_in,
                              void* d_out, int out_size)
{
    const float* vectors = (const float*)d_in[0];
    const float* W       = (const float*)d_in[1];
    const int*   cidx    = (const int*)d_in[2];
    const int*   sidx    = (const int*)d_in[3];
    float*       out     = (float*)d_out;

    int n_edges = in_sizes[2];

    k_zero<<<(NB + 255) / 256, 256>>>();
    k_hist<<<(n_edges + 255) / 256, 256>>>(cidx, sidx, n_edges);
    k_scan<<<1, 1024>>>();
    k_scatter<<<(n_edges + 255) / 256, 256>>>(vectors, cidx, sidx, n_edges);
    // 2 threads per bucket, half assignment is warp-uniform
    k_accum<<<(2 * NB) / 128, 128>>>(W, out);
    // k_accum writes every output element exactly once -> no memset needed
}

// round 4
// speedup vs baseline: 3.8972x; 3.8972x over previous
#include <cuda_runtime.h>

#define NB     131072      // 32768 centers * 4 species
#define MAXE   1048576

namespace {

constexpr float PI_F   = 3.14159265358979323846f;
constexpr float NORM_F = 0.17677669529663687f;   // 1/sqrt(32)

__device__ int    g_cnt[NB];
__device__ int    g_cur[NB];
__device__ int    g_blk[128];
__device__ float4 g_edges[MAXE];

__device__ __forceinline__ void red_add_v4(float* p, float a, float b, float c, float d) {
    unsigned long long gp = __cvta_generic_to_global(p);
    asm volatile("red.global.add.v4.f32 [%0], {%1, %2, %3, %4};"
                 :: "l"(gp), "f"(a), "f"(b), "f"(c), "f"(d)
                 : "memory");
}

// ------------------------------------------------------------ zero counts
__global__ void k_zero() {
    int i = blockIdx.x * blockDim.x + threadIdx.x;   // 32768 threads
    *reinterpret_cast<int4*>(&g_cnt[i * 4]) = make_int4(0, 0, 0, 0);
}

// ------------------------------------------------------------ histogram
__global__ void k_hist(const int* __restrict__ cidx,
                       const int* __restrict__ sidx, int n) {
    int e = blockIdx.x * blockDim.x + threadIdx.x;
    if (e < n) atomicAdd(&g_cnt[cidx[e] * 4 + sidx[e]], 1);
}

// ------------------------------------------------------------ scan (3 steps)
__global__ void k_scanA() {            // 128 blocks x 256 threads
    __shared__ int sm[256];
    int t = threadIdx.x, blk = blockIdx.x;
    int base = blk * 1024 + t * 4;
    int4 c = *reinterpret_cast<const int4*>(&g_cnt[base]);
    int s = c.x + c.y + c.z + c.w;
    sm[t] = s;
    __syncthreads();
    #pragma unroll
    for (int off = 1; off < 256; off <<= 1) {
        int v = (t >= off) ? sm[t - off] : 0;
        __syncthreads();
        sm[t] += v;
        __syncthreads();
    }
    int ex = sm[t] - s;                // exclusive within CTA
    int4 o;
    o.x = ex; o.y = ex + c.x; o.z = o.y + c.y; o.w = o.z + c.z;
    *reinterpret_cast<int4*>(&g_cur[base]) = o;
    if (t == 255) g_blk[blk] = sm[255];
}

__global__ void k_scanB() {            // 1 block x 128 threads
    __shared__ int sm[128];
    int t = threadIdx.x;
    int v = g_blk[t];
    sm[t] = v;
    __syncthreads();
    #pragma unroll
    for (int off = 1; off < 128; off <<= 1) {
        int u = (t >= off) ? sm[t - off] : 0;
        __syncthreads();
        sm[t] += u;
        __syncthreads();
    }
    g_blk[t] = sm[t] - v;              // exclusive block offsets
}

__global__ void k_scanC() {            // 128 blocks x 256 threads
    int t = blockIdx.x * 256 + threadIdx.x;    // 32768 threads, 4 buckets each
    int off = g_blk[t >> 8];
    int4 v = *reinterpret_cast<int4*>(&g_cur[t * 4]);
    v.x += off; v.y += off; v.z += off; v.w += off;
    *reinterpret_cast<int4*>(&g_cur[t * 4]) = v;
}

// ------------------------------------------------------------ scatter (sort)
__global__ void k_scatter(const float* __restrict__ vec,
                          const int* __restrict__ cidx,
                          const int* __restrict__ sidx, int n) {
    int e = blockIdx.x * blockDim.x + threadIdx.x;
    if (e >= n) return;
    int b = cidx[e] * 4 + sidx[e];
    int p = atomicAdd(&g_cur[b], 1);
    g_edges[p] = make_float4(vec[3 * e], vec[3 * e + 1], vec[3 * e + 2],
                             __int_as_float(b));
}

// ------------------------------------------------------------ accumulate
// 128 threads = 4 warps; each warp owns 32 consecutive sorted edges.
// Per lane: full per-edge compute (coalesced). Then equal-bucket segments are
// reduced in registers and flushed with ONE red.v4 per lane per segment.
__global__ __launch_bounds__(128)
void k_accum(const float* __restrict__ W, float* __restrict__ out, int n) {
    __shared__ float sW[384];
    __shared__ float s_sh[4][16 * 33];     // [warp][k*33 + edge]
    __shared__ float s_rad[4][8 * 132];    // [warp][q*132 + edge*4 + c]
    __shared__ int   s_bkt[4][32];

    int t = threadIdx.x, w = t >> 5, lane = t & 31;
    for (int i = t; i < 384; i += 128) sW[i] = W[i];
    __syncthreads();

    int e = blockIdx.x * 128 + t;
    int b = -1;
    float4 v = make_float4(0.f, 0.f, 0.f, 0.f);
    if (e < n) { v = g_edges[e]; b = __float_as_int(v.w); }
    s_bkt[w][lane] = b;

    float rad[32];
    float sh[16];
    #pragma unroll
    for (int i = 0; i < 32; i++) rad[i] = 0.f;
    #pragma unroll
    for (int i = 0; i < 16; i++) sh[i] = 0.f;

    if (b >= 0) {
        float vx = v.x, vy = v.y, vz = v.z;
        float r2   = fmaf(vx, vx, fmaf(vy, vy, vz * vz)) + 1e-12f;
        float rinv = rsqrtf(r2);
        float r    = r2 * rinv;
        float x = vx * rinv, y = vy * rinv, z = vz * rinv;

        float a = (PI_F / 5.0f) * r;
        float s0, c0;
        __sincosf(a, &s0, &c0);
        float tt    = NORM_F * rinv;
        float two_c = 2.0f * c0;
        float phi[12];
        {
            float sm1 = 0.f, sc = s0;
            phi[0] = sc * tt;
            #pragma unroll
            for (int nn = 1; nn < 12; nn++) {
                float s1 = fmaf(two_c, sc, -sm1);
                sm1 = sc; sc = s1;
                phi[nn] = sc * tt;
            }
        }

        // rad[l*8 + n] = sum_b phi[b] * W[l][b][n]
        #pragma unroll
        for (int bb = 0; bb < 12; bb++) {
            float p = phi[bb];
            #pragma unroll
            for (int l = 0; l < 4; l++) {
                #pragma unroll
                for (int nn = 0; nn < 8; nn++)
                    rad[l * 8 + nn] = fmaf(p, sW[l * 96 + bb * 8 + nn], rad[l * 8 + nn]);
            }
        }

        float x2 = x * x, y2 = y * y, z2 = z * z;
        sh[0]  = 0.28209479177387814f;
        sh[1]  = 0.4886025119029199f * y;
        sh[2]  = 0.4886025119029199f * z;
        sh[3]  = 0.4886025119029199f * x;
        sh[4]  = 1.0925484305920792f * x * y;
        sh[5]  = 1.0925484305920792f * y * z;
        sh[6]  = 0.31539156525252005f * fmaf(3.0f, z2, -1.0f);
        sh[7]  = 1.0925484305920792f * x * z;
        sh[8]  = 0.5462742152960396f * (x2 - y2);
        sh[9]  = 0.5900435899266435f * y * fmaf(3.0f, x2, -y2);
        sh[10] = 2.890611442640554f  * x * y * z;
        sh[11] = 0.4570457994644658f * y * fmaf(5.0f, z2, -1.0f);
        sh[12] = 0.3731763325901154f * z * fmaf(5.0f, z2, -3.0f);
        sh[13] = 0.4570457994644658f * x * fmaf(5.0f, z2, -1.0f);
        sh[14] = 1.445305721320277f  * z * (x2 - y2);
        sh[15] = 0.5900435899266435f * x * (x2 - y2);
    }

    // stage to smem (bank-conflict-free layouts)
    #pragma unroll
    for (int k = 0; k < 16; k++) s_sh[w][k * 33 + lane] = sh[k];
    #pragma unroll
    for (int q = 0; q < 8; q++)
        *reinterpret_cast<float4*>(&s_rad[w][q * 132 + lane * 4]) =
            make_float4(rad[q * 4], rad[q * 4 + 1], rad[q * 4 + 2], rad[q * 4 + 3]);
    __syncwarp();

    // segment detection over sorted bucket ids
    int b_up = __shfl_up_sync(0xffffffffu, b, 1);
    bool head = (lane == 0) || (b != b_up);
    unsigned hm = __ballot_sync(0xffffffffu, head);

    int myk  = lane >> 1;
    int half = lane & 1;
    int l    = (myk >= 9) ? 3 : ((myk >= 4) ? 2 : ((myk >= 1) ? 1 : 0));
    int q    = l * 2 + half;
    const float* shrow  = &s_sh[w][myk * 33];
    const float* radrow = &s_rad[w][q * 132];

    unsigned m = hm;
    while (m) {
        int s = __ffs(m) - 1;
        m &= m - 1;
        int e2 = m ? (__ffs(m) - 1) : 32;
        int bs = s_bkt[w][s];
        if (bs >= 0) {
            float ax = 0.f, ay = 0.f, az = 0.f, aw = 0.f;
            for (int i = s; i < e2; i++) {
                float sk = shrow[i];
                float4 r = *reinterpret_cast<const float4*>(&radrow[i * 4]);
                ax = fmaf(sk, r.x, ax);
                ay = fmaf(sk, r.y, ay);
                az = fmaf(sk, r.z, az);
                aw = fmaf(sk, r.w, aw);
            }
            float* p = out + ((bs >> 2) * 512 + myk * 32 + (bs & 3) * 8 + half * 4);
            red_add_v4(p, ax, ay, az, aw);
        }
    }
}

} // namespace

extern "C" void kernel_launch(void* const* d_in, const int* in_sizes, int n_in,
                              void* d_out, int out_size)
{
    const float* vectors = (const float*)d_in[0];
    const float* W       = (const float*)d_in[1];
    const int*   cidx    = (const int*)d_in[2];
    const int*   sidx    = (const int*)d_in[3];
    float*       out     = (float*)d_out;

    int n_edges = in_sizes[2];

    cudaMemsetAsync(d_out, 0, (size_t)out_size * sizeof(float), 0);

    k_zero<<<32768 / 256, 256>>>();
    k_hist<<<(n_edges + 255) / 256, 256>>>(cidx, sidx, n_edges);
    k_scanA<<<128, 256>>>();
    k_scanB<<<1, 128>>>();
    k_scanC<<<128, 256>>>();
    k_scatter<<<(n_edges + 255) / 256, 256>>>(vectors, cidx, sidx, n_edges);
    k_accum<<<(n_edges + 127) / 128, 128>>>(W, out, n_edges);
}